// round 11
// baseline (speedup 1.0000x reference)
#include <cuda_runtime.h>

// ---------------------------------------------------------------------------
// GCN 4-layer forward on GB300 (sm_103a).
// R10: R9 skeleton; GEMM rebuilt with warp-deduplicated smem operands:
//   sWd[k*M+c] = (w,w) dup, k-major  -> warp W load = 128B distinct, 1 phase
//   sXp[p*(K+2)+k] = (row2p, row2p+1) pair-packed -> 64B distinct, 1 phase
//   thread = 8 cols x 1 rowpair, 32 fma2 per k4 -> fma-pipe-bound.
// ---------------------------------------------------------------------------

#define MAX_N 100000
#define MAX_E 800000
#define MAX_G 500

__device__ float g_norm_out[MAX_N];
__device__ float g_norm_in[MAX_N];
__device__ int   g_deg_out[MAX_N];
__device__ int   g_deg_in[MAX_N];
__device__ int   g_row_ptr[MAX_N + 1];
__device__ int   g_cursor[MAX_N];
__device__ int   g_csr_src[MAX_E];
__device__ float g_h0[MAX_N * 128];
__device__ float g_h1[MAX_N * 64];
__device__ float g_gsum[MAX_G * 4];
__device__ int   g_bsum[32];
__device__ int   g_sync[4];

typedef unsigned long long ull;

__device__ __forceinline__ ull pk(float lo, float hi) {
    ull r; asm("mov.b64 %0, {%1,%2};" : "=l"(r) : "f"(lo), "f"(hi)); return r;
}
__device__ __forceinline__ void fma2(ull& d, ull a, ull b) {
    asm("fma.rn.f32x2 %0, %1, %2, %0;" : "+l"(d) : "l"(a), "l"(b));
}
__device__ __forceinline__ float2 upk(ull v) {
    float2 f; asm("mov.b64 {%0,%1}, %2;" : "=f"(f.x), "=f"(f.y) : "l"(v)); return f;
}

// Device-wide barrier: all blocks co-resident (148 blocks, 1/SM).
__device__ __forceinline__ void gbar(int idx, int nb) {
    __syncthreads();
    if (threadIdx.x == 0) {
        __threadfence();
        atomicAdd(&g_sync[idx], 1);
        while (atomicAdd(&g_sync[idx], 0) < nb) { }
    }
    __syncthreads();
}

// ---------------------------------------------------------------------------
// Persistent preprocessing: degrees -> scan(+norms) -> csr_fill (R9 verbatim).
// ---------------------------------------------------------------------------
__global__ void __launch_bounds__(1024, 1)
prep_kernel(const int* __restrict__ src, const int* __restrict__ dst,
            int n, int e, int nsb) {
    const int NBK = gridDim.x;
    int b = blockIdx.x, t = threadIdx.x, lane = t & 31, w = t >> 5;
    int gtid = b * 1024 + t;
    int gsz = NBK * 1024;

    for (int i = gtid; i < e; i += gsz) {
        atomicAdd(&g_deg_out[src[i]], 1);
        atomicAdd(&g_deg_in[dst[i]], 1);
    }
    gbar(0, NBK);

    __shared__ int swarp[32];
    __shared__ int s_boff;
    int4 v = make_int4(0, 0, 0, 0);
    int s = 0, ts = 0;
    int i0 = b * 4096 + t * 4;
    if (b < nsb) {
        if (i0 + 3 < n) v = *(const int4*)&g_deg_in[i0];
        else {
            if (i0     < n) v.x = g_deg_in[i0];
            if (i0 + 1 < n) v.y = g_deg_in[i0 + 1];
            if (i0 + 2 < n) v.z = g_deg_in[i0 + 2];
            if (i0 + 3 < n) v.w = g_deg_in[i0 + 3];
        }
        if (i0 < n) {
            g_norm_in[i0] = rsqrtf(fmaxf((float)v.x, 1.f));
            g_norm_out[i0] = rsqrtf(fmaxf((float)g_deg_out[i0], 1.f));
        }
        if (i0 + 1 < n) {
            g_norm_in[i0 + 1] = rsqrtf(fmaxf((float)v.y, 1.f));
            g_norm_out[i0 + 1] = rsqrtf(fmaxf((float)g_deg_out[i0 + 1], 1.f));
        }
        if (i0 + 2 < n) {
            g_norm_in[i0 + 2] = rsqrtf(fmaxf((float)v.z, 1.f));
            g_norm_out[i0 + 2] = rsqrtf(fmaxf((float)g_deg_out[i0 + 2], 1.f));
        }
        if (i0 + 3 < n) {
            g_norm_in[i0 + 3] = rsqrtf(fmaxf((float)v.w, 1.f));
            g_norm_out[i0 + 3] = rsqrtf(fmaxf((float)g_deg_out[i0 + 3], 1.f));
        }
        ts = v.x + v.y + v.z + v.w;
        s = ts;
        #pragma unroll
        for (int o = 1; o < 32; o <<= 1) {
            int x = __shfl_up_sync(0xffffffffu, s, o);
            if (lane >= o) s += x;
        }
        if (lane == 31) swarp[w] = s;
        __syncthreads();
        if (w == 0) {
            int ws = swarp[lane];
            #pragma unroll
            for (int o = 1; o < 32; o <<= 1) {
                int x = __shfl_up_sync(0xffffffffu, ws, o);
                if (lane >= o) ws += x;
            }
            swarp[lane] = ws;
        }
        __syncthreads();
        if (t == 0) g_bsum[b] = swarp[31];
    }
    gbar(1, NBK);

    if (b < nsb) {
        if (w == 0) {
            int acc = (lane < b) ? g_bsum[lane] : 0;
            #pragma unroll
            for (int o = 16; o; o >>= 1) acc += __shfl_down_sync(0xffffffffu, acc, o);
            if (lane == 0) {
                s_boff = acc;
                if (b == nsb - 1) g_row_ptr[n] = acc + swarp[31];
            }
        }
        __syncthreads();
        int pre = (w > 0) ? swarp[w - 1] : 0;
        int e0 = s_boff + pre + s - ts;
        int e1 = e0 + v.x, e2 = e1 + v.y, e3 = e2 + v.z;
        if (i0     < n) { g_row_ptr[i0]     = e0; g_cursor[i0]     = e0; }
        if (i0 + 1 < n) { g_row_ptr[i0 + 1] = e1; g_cursor[i0 + 1] = e1; }
        if (i0 + 2 < n) { g_row_ptr[i0 + 2] = e2; g_cursor[i0 + 2] = e2; }
        if (i0 + 3 < n) { g_row_ptr[i0 + 3] = e3; g_cursor[i0 + 3] = e3; }
    }
    gbar(2, NBK);

    for (int i = gtid; i < e; i += gsz) {
        int p = atomicAdd(&g_cursor[dst[i]], 1);
        g_csr_src[p] = src[i];
    }
}

// ---------------------------------------------------------------------------
// Gather-aggregate DIM=64: warp/node, 8-way MLP unroll (R9 verbatim).
// ---------------------------------------------------------------------------
template<bool RELU, bool HASB, bool SRCSCALE>
__global__ void agg64_kernel(const float* __restrict__ hin,
                             float* __restrict__ hout,
                             const float* __restrict__ bias, int n) {
    int node = (blockIdx.x * blockDim.x + threadIdx.x) >> 5;
    int l = threadIdx.x & 31;
    if (node >= n) return;
    int beg = g_row_ptr[node];
    int end = g_row_ptr[node + 1];
    float ni = g_norm_in[node];
    const float* base = hin + l * 2;
    float2 a0 = {0,0}, a1 = {0,0}, a2 = {0,0}, a3 = {0,0};
    float2 a4 = {0,0}, a5 = {0,0}, a6 = {0,0}, a7 = {0,0};
    int e = beg;
    for (; e + 7 < end; e += 8) {
        int s0 = g_csr_src[e],     s1 = g_csr_src[e + 1];
        int s2 = g_csr_src[e + 2], s3 = g_csr_src[e + 3];
        int s4 = g_csr_src[e + 4], s5 = g_csr_src[e + 5];
        int s6 = g_csr_src[e + 6], s7 = g_csr_src[e + 7];
        float2 v0 = *(const float2*)(base + s0 * 64);
        float2 v1 = *(const float2*)(base + s1 * 64);
        float2 v2 = *(const float2*)(base + s2 * 64);
        float2 v3 = *(const float2*)(base + s3 * 64);
        float2 v4 = *(const float2*)(base + s4 * 64);
        float2 v5 = *(const float2*)(base + s5 * 64);
        float2 v6 = *(const float2*)(base + s6 * 64);
        float2 v7 = *(const float2*)(base + s7 * 64);
        if (SRCSCALE) {
            float n0 = g_norm_out[s0], n1 = g_norm_out[s1];
            float n2 = g_norm_out[s2], n3 = g_norm_out[s3];
            float n4 = g_norm_out[s4], n5 = g_norm_out[s5];
            float n6 = g_norm_out[s6], n7 = g_norm_out[s7];
            a0.x = fmaf(v0.x, n0, a0.x); a0.y = fmaf(v0.y, n0, a0.y);
            a1.x = fmaf(v1.x, n1, a1.x); a1.y = fmaf(v1.y, n1, a1.y);
            a2.x = fmaf(v2.x, n2, a2.x); a2.y = fmaf(v2.y, n2, a2.y);
            a3.x = fmaf(v3.x, n3, a3.x); a3.y = fmaf(v3.y, n3, a3.y);
            a4.x = fmaf(v4.x, n4, a4.x); a4.y = fmaf(v4.y, n4, a4.y);
            a5.x = fmaf(v5.x, n5, a5.x); a5.y = fmaf(v5.y, n5, a5.y);
            a6.x = fmaf(v6.x, n6, a6.x); a6.y = fmaf(v6.y, n6, a6.y);
            a7.x = fmaf(v7.x, n7, a7.x); a7.y = fmaf(v7.y, n7, a7.y);
        } else {
            a0.x += v0.x; a0.y += v0.y; a1.x += v1.x; a1.y += v1.y;
            a2.x += v2.x; a2.y += v2.y; a3.x += v3.x; a3.y += v3.y;
            a4.x += v4.x; a4.y += v4.y; a5.x += v5.x; a5.y += v5.y;
            a6.x += v6.x; a6.y += v6.y; a7.x += v7.x; a7.y += v7.y;
        }
    }
    for (; e < end; e++) {
        int s0 = g_csr_src[e];
        float2 v = *(const float2*)(base + s0 * 64);
        if (SRCSCALE) {
            float n0 = g_norm_out[s0];
            a0.x = fmaf(v.x, n0, a0.x); a0.y = fmaf(v.y, n0, a0.y);
        } else { a0.x += v.x; a0.y += v.y; }
    }
    float ax = ((a0.x + a1.x) + (a2.x + a3.x)) + ((a4.x + a5.x) + (a6.x + a7.x));
    float ay = ((a0.y + a1.y) + (a2.y + a3.y)) + ((a4.y + a5.y) + (a6.y + a7.y));
    ax *= ni; ay *= ni;
    if (HASB) { ax += bias[l * 2]; ay += bias[l * 2 + 1]; }
    if (RELU) { ax = fmaxf(ax, 0.0f); ay = fmaxf(ay, 0.0f); }
    float2 o; o.x = ax; o.y = ay;
    *(float2*)&hout[node * 64 + l * 2] = o;
}

// ---------------------------------------------------------------------------
// f32x2 GEMM, warp-deduplicated operands:
//   sWd[k*M + c] = (W[k][c], W[k][c])             (k-major, duplicated)
//   sXp[p*KP + k] = (in[2p][k], in[2p+1][k])      (row-pair packed, KP=K+2)
//   thread: 8 cols x 1 rowpair; warp: 8 distinct col-groups x 4 rowpairs
//   -> W LDS.128 = 128B distinct (1 phase), X LDS.128 = 64B (1 phase).
// ---------------------------------------------------------------------------
template<int K, int M, bool RELU, bool BIAS, bool RSCALE, int MAXB>
__global__ void __launch_bounds__(256, MAXB)
gemm_kernel(const float* __restrict__ in, const float* __restrict__ W,
            const float* __restrict__ bias, float* __restrict__ out, int n) {
    constexpr int THREADS = 256;
    constexpr int CGT = M / 8;                 // col-groups total
    constexpr int CGW = (CGT < 8) ? CGT : 8;   // col-groups per warp
    constexpr int WC = CGT / CGW;              // warps across cols
    constexpr int PAIRS = THREADS / CGT;       // rowpairs per tile
    constexpr int RTILE = 2 * PAIRS;
    constexpr int KV = K / 4;
    constexpr int KP = K + 2;

    extern __shared__ char smx[];
    ull* sWd = (ull*)smx;                          // K*M
    ull* sXp = (ull*)(smx + (size_t)K * M * 8);    // PAIRS*KP

    const int tid = threadIdx.x;
    // Stage W duplicated, k-major
    for (int idx = tid; idx < K * M; idx += THREADS) {
        float w = W[idx];
        sWd[idx] = pk(w, w);
    }

    int wp = tid >> 5, lane = tid & 31;
    int cg = (lane % CGW) + (wp % WC) * CGW;
    int rg = (lane / CGW) + (wp / WC) * (32 / CGW);
    int c0 = cg * 8;

    float4 bva = make_float4(0.f, 0.f, 0.f, 0.f);
    float4 bvb = make_float4(0.f, 0.f, 0.f, 0.f);
    if (BIAS) {
        bva = *(const float4*)&bias[c0];
        bvb = *(const float4*)&bias[c0 + 4];
    }

    const float4* in4 = (const float4*)in;
    int ntiles = (n + RTILE - 1) / RTILE;
    for (int t = blockIdx.x; t < ntiles; t += gridDim.x) {
        int row0 = t * RTILE;
        __syncthreads();
        // Stage X row-pair packed
        for (int idx = tid; idx < PAIRS * KV; idx += THREADS) {
            int p = idx / KV, k4 = idx % KV;
            int ra = row0 + 2 * p;
            float4 a = (ra < n) ? in4[(size_t)ra * KV + k4] : make_float4(0.f,0.f,0.f,0.f);
            float4 b = (ra + 1 < n) ? in4[(size_t)(ra + 1) * KV + k4] : make_float4(0.f,0.f,0.f,0.f);
            ull* d = &sXp[p * KP + k4 * 4];
            d[0] = pk(a.x, b.x); d[1] = pk(a.y, b.y);
            d[2] = pk(a.z, b.z); d[3] = pk(a.w, b.w);
        }
        __syncthreads();

        ull acc[8];
        #pragma unroll
        for (int c = 0; c < 8; c++) acc[c] = 0ULL;

        const ull* xrow = &sXp[rg * KP];
        #pragma unroll 4
        for (int k4 = 0; k4 < KV; k4++) {
            ulonglong2 xa = *(const ulonglong2*)&xrow[k4 * 4];
            ulonglong2 xb = *(const ulonglong2*)&xrow[k4 * 4 + 2];
            ull xk0 = xa.x, xk1 = xa.y, xk2 = xb.x, xk3 = xb.y;
            #pragma unroll
            for (int kk = 0; kk < 4; kk++) {
                ull xv = (kk == 0) ? xk0 : (kk == 1) ? xk1 : (kk == 2) ? xk2 : xk3;
                const ull* wk = &sWd[(k4 * 4 + kk) * M + c0];
                ulonglong2 w0 = *(const ulonglong2*)wk;
                ulonglong2 w1 = *(const ulonglong2*)(wk + 2);
                ulonglong2 w2 = *(const ulonglong2*)(wk + 4);
                ulonglong2 w3 = *(const ulonglong2*)(wk + 6);
                fma2(acc[0], xv, w0.x); fma2(acc[1], xv, w0.y);
                fma2(acc[2], xv, w1.x); fma2(acc[3], xv, w1.y);
                fma2(acc[4], xv, w2.x); fma2(acc[5], xv, w2.y);
                fma2(acc[6], xv, w3.x); fma2(acc[7], xv, w3.y);
            }
        }

        int ra = row0 + 2 * rg, rb = ra + 1;
        float2 f0 = upk(acc[0]), f1 = upk(acc[1]), f2 = upk(acc[2]), f3 = upk(acc[3]);
        float2 f4 = upk(acc[4]), f5 = upk(acc[5]), f6 = upk(acc[6]), f7 = upk(acc[7]);
        float4 va1 = make_float4(f0.x, f1.x, f2.x, f3.x);
        float4 va2 = make_float4(f4.x, f5.x, f6.x, f7.x);
        float4 vb1 = make_float4(f0.y, f1.y, f2.y, f3.y);
        float4 vb2 = make_float4(f4.y, f5.y, f6.y, f7.y);
        if (BIAS) {
            va1.x += bva.x; va1.y += bva.y; va1.z += bva.z; va1.w += bva.w;
            va2.x += bvb.x; va2.y += bvb.y; va2.z += bvb.z; va2.w += bvb.w;
            vb1.x += bva.x; vb1.y += bva.y; vb1.z += bva.z; vb1.w += bva.w;
            vb2.x += bvb.x; vb2.y += bvb.y; vb2.z += bvb.z; vb2.w += bvb.w;
        }
        if (RSCALE) {
            float sa = (ra < n) ? g_norm_out[ra] : 0.f;
            float sb = (rb < n) ? g_norm_out[rb] : 0.f;
            va1.x *= sa; va1.y *= sa; va1.z *= sa; va1.w *= sa;
            va2.x *= sa; va2.y *= sa; va2.z *= sa; va2.w *= sa;
            vb1.x *= sb; vb1.y *= sb; vb1.z *= sb; vb1.w *= sb;
            vb2.x *= sb; vb2.y *= sb; vb2.z *= sb; vb2.w *= sb;
        }
        if (RELU) {
            va1.x = fmaxf(va1.x, 0.f); va1.y = fmaxf(va1.y, 0.f);
            va1.z = fmaxf(va1.z, 0.f); va1.w = fmaxf(va1.w, 0.f);
            va2.x = fmaxf(va2.x, 0.f); va2.y = fmaxf(va2.y, 0.f);
            va2.z = fmaxf(va2.z, 0.f); va2.w = fmaxf(va2.w, 0.f);
            vb1.x = fmaxf(vb1.x, 0.f); vb1.y = fmaxf(vb1.y, 0.f);
            vb1.z = fmaxf(vb1.z, 0.f); vb1.w = fmaxf(vb1.w, 0.f);
            vb2.x = fmaxf(vb2.x, 0.f); vb2.y = fmaxf(vb2.y, 0.f);
            vb2.z = fmaxf(vb2.z, 0.f); vb2.w = fmaxf(vb2.w, 0.f);
        }
        if (ra < n) {
            *(float4*)&out[(size_t)ra * M + c0]     = va1;
            *(float4*)&out[(size_t)ra * M + c0 + 4] = va2;
        }
        if (rb < n) {
            *(float4*)&out[(size_t)rb * M + c0]     = vb1;
            *(float4*)&out[(size_t)rb * M + c0 + 4] = vb2;
        }
    }
}

// ---------------------------------------------------------------------------
// Fused: agg(h,32) *norm_in +b3, relu -> @W4[32,4] -> *norm_out (R9 verbatim)
// ---------------------------------------------------------------------------
__global__ void agg32_gemm4(const float* __restrict__ hin,
                            const float* __restrict__ W4,
                            const float* __restrict__ b3,
                            float* __restrict__ hout, int n) {
    int warp = (blockIdx.x * blockDim.x + threadIdx.x) >> 5;
    int lane = threadIdx.x & 31;
    if (warp >= n) return;
    int node = warp;
    float4 w4 = *(const float4*)&W4[lane * 4];
    float bl = b3[lane];
    int beg = g_row_ptr[node], end = g_row_ptr[node + 1];
    const float* base = hin + lane;
    float a0 = 0, a1 = 0, a2 = 0, a3 = 0;
    float a4 = 0, a5 = 0, a6 = 0, a7 = 0;
    int e = beg;
    for (; e + 7 < end; e += 8) {
        a0 += base[g_csr_src[e] * 32];
        a1 += base[g_csr_src[e + 1] * 32];
        a2 += base[g_csr_src[e + 2] * 32];
        a3 += base[g_csr_src[e + 3] * 32];
        a4 += base[g_csr_src[e + 4] * 32];
        a5 += base[g_csr_src[e + 5] * 32];
        a6 += base[g_csr_src[e + 6] * 32];
        a7 += base[g_csr_src[e + 7] * 32];
    }
    for (; e < end; e++) a0 += base[g_csr_src[e] * 32];
    float a = ((a0 + a1) + (a2 + a3)) + ((a4 + a5) + (a6 + a7));
    a = fmaxf(fmaf(a, g_norm_in[node], bl), 0.0f);
    float4 y;
    y.x = a * w4.x; y.y = a * w4.y; y.z = a * w4.z; y.w = a * w4.w;
    #pragma unroll
    for (int o = 16; o; o >>= 1) {
        y.x += __shfl_xor_sync(0xffffffffu, y.x, o);
        y.y += __shfl_xor_sync(0xffffffffu, y.y, o);
        y.z += __shfl_xor_sync(0xffffffffu, y.z, o);
        y.w += __shfl_xor_sync(0xffffffffu, y.w, o);
    }
    if (lane == 0) {
        float s = g_norm_out[node];
        y.x *= s; y.y *= s; y.z *= s; y.w *= s;
        *(float4*)&hout[(size_t)node * 4] = y;
    }
}

// ---------------------------------------------------------------------------
// Final: agg(h,4) * norm_in + b4 -> per-graph atomic sum (R9 verbatim).
// ---------------------------------------------------------------------------
__global__ void agg4_readout(const float* __restrict__ hin,
                             const float* __restrict__ b4,
                             const int* __restrict__ gid, int n) {
    int warp = (blockIdx.x * blockDim.x + threadIdx.x) >> 5;
    int lane = threadIdx.x & 31;
    int node = warp * 8 + (lane >> 2);
    int l = lane & 3;
    float v = 0.f;
    int g = 0;
    bool valid = node < n;
    if (valid) {
        int beg = g_row_ptr[node], end = g_row_ptr[node + 1];
        float a0 = 0, a1 = 0, a2 = 0, a3 = 0;
        int e = beg;
        for (; e + 3 < end; e += 4) {
            a0 += hin[g_csr_src[e] * 4 + l];
            a1 += hin[g_csr_src[e + 1] * 4 + l];
            a2 += hin[g_csr_src[e + 2] * 4 + l];
            a3 += hin[g_csr_src[e + 3] * 4 + l];
        }
        for (; e < end; e++) a0 += hin[g_csr_src[e] * 4 + l];
        v = fmaf(((a0 + a1) + (a2 + a3)), g_norm_in[node], b4[l]);
        g = gid[node];
    }
    unsigned act = __ballot_sync(0xffffffffu, valid);
    if (act == 0xffffffffu) {
        int g0 = __shfl_sync(0xffffffffu, g, 0);
        if (__all_sync(0xffffffffu, g == g0)) {
            v += __shfl_xor_sync(0xffffffffu, v, 4);
            v += __shfl_xor_sync(0xffffffffu, v, 8);
            v += __shfl_xor_sync(0xffffffffu, v, 16);
            if (lane < 4) atomicAdd(&g_gsum[g0 * 4 + lane], v);
            return;
        }
    }
    if (valid) atomicAdd(&g_gsum[g * 4 + l], v);
}

// Per-graph mean; counts via binary search over sorted gid.
__global__ void graph_mean_kernel(float* __restrict__ out,
                                  const int* __restrict__ gid, int n, int g) {
    int i = blockIdx.x * blockDim.x + threadIdx.x;
    if (i >= g) return;
    int lo = 0, hi = n;
    while (lo < hi) { int mid = (lo + hi) >> 1; if (gid[mid] < i) lo = mid + 1; else hi = mid; }
    int lo2 = lo, hi2 = n;
    while (lo2 < hi2) { int mid = (lo2 + hi2) >> 1; if (gid[mid] < i + 1) lo2 = mid + 1; else hi2 = mid; }
    float c = fmaxf((float)(lo2 - lo), 1.0f);
    float4 sres = *(const float4*)&g_gsum[i * 4];
    out[i * 4 + 0] = sres.x / c;
    out[i * 4 + 1] = sres.y / c;
    out[i * 4 + 2] = sres.z / c;
    out[i * 4 + 3] = sres.w / c;
}

// ---------------------------------------------------------------------------
extern "C" void kernel_launch(void* const* d_in, const int* in_sizes, int n_in,
                              void* d_out, int out_size) {
    const float* x  = (const float*)d_in[0];
    const float* W1 = (const float*)d_in[1];
    const float* b1 = (const float*)d_in[2];
    const float* W2 = (const float*)d_in[3];
    const float* b2 = (const float*)d_in[4];
    const float* W3 = (const float*)d_in[5];
    const float* b3 = (const float*)d_in[6];
    const float* W4 = (const float*)d_in[7];
    const float* b4 = (const float*)d_in[8];
    const int* src = (const int*)d_in[9];
    const int* dst = (const int*)d_in[10];
    const int* gid = (const int*)d_in[11];
    float* out = (float*)d_out;

    int n = in_sizes[0] / 64;
    int e = in_sizes[9];
    int g = out_size / 4;
    int nsb = (n + 4095) / 4096;

    float *h0, *h1;
    void *p_dego, *p_degi, *p_gsum, *p_sync;
    cudaGetSymbolAddress((void**)&h0, g_h0);
    cudaGetSymbolAddress((void**)&h1, g_h1);
    cudaGetSymbolAddress(&p_dego, g_deg_out);
    cudaGetSymbolAddress(&p_degi, g_deg_in);
    cudaGetSymbolAddress(&p_gsum, g_gsum);
    cudaGetSymbolAddress(&p_sync, g_sync);

    const int T = 256;
    auto blocks = [](int work, int t) { return (work + t - 1) / t; };
    auto warp_grid = [&](int nodes_per_warp) {
        int warps = (n + nodes_per_warp - 1) / nodes_per_warp;
        return (warps * 32 + T - 1) / T;
    };

    // GEMM dynamic smem: sWd = K*M*8, sXp = PAIRS*(K+2)*8
    // gemm1 (64->128): 65536 + 16*66*8  = 74 KB  (occ 2)
    // gemm2 (128->64): 65536 + 32*130*8 = 97 KB  (occ 2)
    // gemm3 (64->32):  16384 + 64*66*8  = 49 KB  (occ 4)
    const int SM1 = 64 * 128 * 8 + 16 * 66 * 8;
    const int SM2 = 128 * 64 * 8 + 32 * 130 * 8;
    const int SM3 = 64 * 32 * 8 + 64 * 66 * 8;
    cudaFuncSetAttribute((const void*)gemm_kernel<64, 128, true, true, false, 2>,
                         cudaFuncAttributeMaxDynamicSharedMemorySize, SM1);
    cudaFuncSetAttribute((const void*)gemm_kernel<128, 64, false, false, true, 2>,
                         cudaFuncAttributeMaxDynamicSharedMemorySize, SM2);
    cudaFuncSetAttribute((const void*)gemm_kernel<64, 32, false, false, true, 4>,
                         cudaFuncAttributeMaxDynamicSharedMemorySize, SM3);

    // Zeroing via memset nodes (not kernel launches)
    cudaMemsetAsync(p_dego, 0, (size_t)n * 4);
    cudaMemsetAsync(p_degi, 0, (size_t)n * 4);
    cudaMemsetAsync(p_gsum, 0, (size_t)g * 4 * 4);
    cudaMemsetAsync(p_sync, 0, 4 * 4);

    // Launch 1: fused preprocessing
    prep_kernel<<<148, 1024>>>(src, dst, n, e, nsb);

    // Launch 2: agg(x * norm_out) -> *norm_in
    agg64_kernel<false, false, true><<<warp_grid(1), T>>>(x, h1, nullptr, n);
    // Launch 3: @W1 + b1, relu
    gemm_kernel<64, 128, true, true, false, 2><<<296, 256, SM1>>>(h1, W1, b1, h0, n);
    // Launch 4 (profiled): @W2, *norm_out
    gemm_kernel<128, 64, false, false, true, 2><<<296, 256, SM2>>>(h0, W2, nullptr, h1, n);
    // Launch 5: agg -> *norm_in + b2, relu
    agg64_kernel<true, true, false><<<warp_grid(1), T>>>(h1, h0, b2, n);
    // Launch 6: @W3, *norm_out
    gemm_kernel<64, 32, false, false, true, 4><<<592, 256, SM3>>>(h0, W3, nullptr, h1, n);
    // Launch 7: agg32 -> +b3, relu -> @W4 -> *norm_out
    agg32_gemm4<<<warp_grid(1), T>>>(h1, W4, b3, h0, n);
    // Launch 8: agg4 + readout
    agg4_readout<<<warp_grid(8), T>>>(h0, b4, gid, n);
    // Launch 9: per-graph mean
    graph_mean_kernel<<<blocks(g, T), T>>>(out, gid, n, g);
}

// round 12
// speedup vs baseline: 2.5643x; 2.5643x over previous
#include <cuda_runtime.h>

// ---------------------------------------------------------------------------
// GCN 4-layer forward on GB300 (sm_103a).
// R11: R10 skeleton (persistent prep, 8-way agg64, fused agg32+gemm4, fused
// readout) + the R2-proven plain-FFMA GEMM with K+4 padded W layout
// (verified conflict-free: col stride (K+4)*4B -> 16B steps mod 128B).
// All f32x2/ull GEMM experiments abandoned (R4/R5/R7/R10 all regressed).
// ---------------------------------------------------------------------------

#define MAX_N 100000
#define MAX_E 800000
#define MAX_G 500

__device__ float g_norm_out[MAX_N];
__device__ float g_norm_in[MAX_N];
__device__ int   g_deg_out[MAX_N];
__device__ int   g_deg_in[MAX_N];
__device__ int   g_row_ptr[MAX_N + 1];
__device__ int   g_cursor[MAX_N];
__device__ int   g_csr_src[MAX_E];
__device__ float g_h0[MAX_N * 128];
__device__ float g_h1[MAX_N * 64];
__device__ float g_gsum[MAX_G * 4];
__device__ int   g_bsum[32];
__device__ int   g_sync[4];

// Device-wide barrier: all blocks co-resident (148 blocks, 1/SM).
__device__ __forceinline__ void gbar(int idx, int nb) {
    __syncthreads();
    if (threadIdx.x == 0) {
        __threadfence();
        atomicAdd(&g_sync[idx], 1);
        while (atomicAdd(&g_sync[idx], 0) < nb) { }
    }
    __syncthreads();
}

// ---------------------------------------------------------------------------
// Persistent preprocessing: degrees -> scan(+norms) -> csr_fill.
// ---------------------------------------------------------------------------
__global__ void __launch_bounds__(1024, 1)
prep_kernel(const int* __restrict__ src, const int* __restrict__ dst,
            int n, int e, int nsb) {
    const int NBK = gridDim.x;
    int b = blockIdx.x, t = threadIdx.x, lane = t & 31, w = t >> 5;
    int gtid = b * 1024 + t;
    int gsz = NBK * 1024;

    for (int i = gtid; i < e; i += gsz) {
        atomicAdd(&g_deg_out[src[i]], 1);
        atomicAdd(&g_deg_in[dst[i]], 1);
    }
    gbar(0, NBK);

    __shared__ int swarp[32];
    __shared__ int s_boff;
    int4 v = make_int4(0, 0, 0, 0);
    int s = 0, ts = 0;
    int i0 = b * 4096 + t * 4;
    if (b < nsb) {
        if (i0 + 3 < n) v = *(const int4*)&g_deg_in[i0];
        else {
            if (i0     < n) v.x = g_deg_in[i0];
            if (i0 + 1 < n) v.y = g_deg_in[i0 + 1];
            if (i0 + 2 < n) v.z = g_deg_in[i0 + 2];
            if (i0 + 3 < n) v.w = g_deg_in[i0 + 3];
        }
        if (i0 < n) {
            g_norm_in[i0] = rsqrtf(fmaxf((float)v.x, 1.f));
            g_norm_out[i0] = rsqrtf(fmaxf((float)g_deg_out[i0], 1.f));
        }
        if (i0 + 1 < n) {
            g_norm_in[i0 + 1] = rsqrtf(fmaxf((float)v.y, 1.f));
            g_norm_out[i0 + 1] = rsqrtf(fmaxf((float)g_deg_out[i0 + 1], 1.f));
        }
        if (i0 + 2 < n) {
            g_norm_in[i0 + 2] = rsqrtf(fmaxf((float)v.z, 1.f));
            g_norm_out[i0 + 2] = rsqrtf(fmaxf((float)g_deg_out[i0 + 2], 1.f));
        }
        if (i0 + 3 < n) {
            g_norm_in[i0 + 3] = rsqrtf(fmaxf((float)v.w, 1.f));
            g_norm_out[i0 + 3] = rsqrtf(fmaxf((float)g_deg_out[i0 + 3], 1.f));
        }
        ts = v.x + v.y + v.z + v.w;
        s = ts;
        #pragma unroll
        for (int o = 1; o < 32; o <<= 1) {
            int x = __shfl_up_sync(0xffffffffu, s, o);
            if (lane >= o) s += x;
        }
        if (lane == 31) swarp[w] = s;
        __syncthreads();
        if (w == 0) {
            int ws = swarp[lane];
            #pragma unroll
            for (int o = 1; o < 32; o <<= 1) {
                int x = __shfl_up_sync(0xffffffffu, ws, o);
                if (lane >= o) ws += x;
            }
            swarp[lane] = ws;
        }
        __syncthreads();
        if (t == 0) g_bsum[b] = swarp[31];
    }
    gbar(1, NBK);

    if (b < nsb) {
        if (w == 0) {
            int acc = (lane < b) ? g_bsum[lane] : 0;
            #pragma unroll
            for (int o = 16; o; o >>= 1) acc += __shfl_down_sync(0xffffffffu, acc, o);
            if (lane == 0) {
                s_boff = acc;
                if (b == nsb - 1) g_row_ptr[n] = acc + swarp[31];
            }
        }
        __syncthreads();
        int pre = (w > 0) ? swarp[w - 1] : 0;
        int e0 = s_boff + pre + s - ts;
        int e1 = e0 + v.x, e2 = e1 + v.y, e3 = e2 + v.z;
        if (i0     < n) { g_row_ptr[i0]     = e0; g_cursor[i0]     = e0; }
        if (i0 + 1 < n) { g_row_ptr[i0 + 1] = e1; g_cursor[i0 + 1] = e1; }
        if (i0 + 2 < n) { g_row_ptr[i0 + 2] = e2; g_cursor[i0 + 2] = e2; }
        if (i0 + 3 < n) { g_row_ptr[i0 + 3] = e3; g_cursor[i0 + 3] = e3; }
    }
    gbar(2, NBK);

    for (int i = gtid; i < e; i += gsz) {
        int p = atomicAdd(&g_cursor[dst[i]], 1);
        g_csr_src[p] = src[i];
    }
}

// ---------------------------------------------------------------------------
// Gather-aggregate DIM=64: warp/node, 8-way MLP unroll.
// ---------------------------------------------------------------------------
template<bool RELU, bool HASB, bool SRCSCALE>
__global__ void agg64_kernel(const float* __restrict__ hin,
                             float* __restrict__ hout,
                             const float* __restrict__ bias, int n) {
    int node = (blockIdx.x * blockDim.x + threadIdx.x) >> 5;
    int l = threadIdx.x & 31;
    if (node >= n) return;
    int beg = g_row_ptr[node];
    int end = g_row_ptr[node + 1];
    float ni = g_norm_in[node];
    const float* base = hin + l * 2;
    float2 a0 = {0,0}, a1 = {0,0}, a2 = {0,0}, a3 = {0,0};
    float2 a4 = {0,0}, a5 = {0,0}, a6 = {0,0}, a7 = {0,0};
    int e = beg;
    for (; e + 7 < end; e += 8) {
        int s0 = g_csr_src[e],     s1 = g_csr_src[e + 1];
        int s2 = g_csr_src[e + 2], s3 = g_csr_src[e + 3];
        int s4 = g_csr_src[e + 4], s5 = g_csr_src[e + 5];
        int s6 = g_csr_src[e + 6], s7 = g_csr_src[e + 7];
        float2 v0 = *(const float2*)(base + s0 * 64);
        float2 v1 = *(const float2*)(base + s1 * 64);
        float2 v2 = *(const float2*)(base + s2 * 64);
        float2 v3 = *(const float2*)(base + s3 * 64);
        float2 v4 = *(const float2*)(base + s4 * 64);
        float2 v5 = *(const float2*)(base + s5 * 64);
        float2 v6 = *(const float2*)(base + s6 * 64);
        float2 v7 = *(const float2*)(base + s7 * 64);
        if (SRCSCALE) {
            float n0 = g_norm_out[s0], n1 = g_norm_out[s1];
            float n2 = g_norm_out[s2], n3 = g_norm_out[s3];
            float n4 = g_norm_out[s4], n5 = g_norm_out[s5];
            float n6 = g_norm_out[s6], n7 = g_norm_out[s7];
            a0.x = fmaf(v0.x, n0, a0.x); a0.y = fmaf(v0.y, n0, a0.y);
            a1.x = fmaf(v1.x, n1, a1.x); a1.y = fmaf(v1.y, n1, a1.y);
            a2.x = fmaf(v2.x, n2, a2.x); a2.y = fmaf(v2.y, n2, a2.y);
            a3.x = fmaf(v3.x, n3, a3.x); a3.y = fmaf(v3.y, n3, a3.y);
            a4.x = fmaf(v4.x, n4, a4.x); a4.y = fmaf(v4.y, n4, a4.y);
            a5.x = fmaf(v5.x, n5, a5.x); a5.y = fmaf(v5.y, n5, a5.y);
            a6.x = fmaf(v6.x, n6, a6.x); a6.y = fmaf(v6.y, n6, a6.y);
            a7.x = fmaf(v7.x, n7, a7.x); a7.y = fmaf(v7.y, n7, a7.y);
        } else {
            a0.x += v0.x; a0.y += v0.y; a1.x += v1.x; a1.y += v1.y;
            a2.x += v2.x; a2.y += v2.y; a3.x += v3.x; a3.y += v3.y;
            a4.x += v4.x; a4.y += v4.y; a5.x += v5.x; a5.y += v5.y;
            a6.x += v6.x; a6.y += v6.y; a7.x += v7.x; a7.y += v7.y;
        }
    }
    for (; e < end; e++) {
        int s0 = g_csr_src[e];
        float2 v = *(const float2*)(base + s0 * 64);
        if (SRCSCALE) {
            float n0 = g_norm_out[s0];
            a0.x = fmaf(v.x, n0, a0.x); a0.y = fmaf(v.y, n0, a0.y);
        } else { a0.x += v.x; a0.y += v.y; }
    }
    float ax = ((a0.x + a1.x) + (a2.x + a3.x)) + ((a4.x + a5.x) + (a6.x + a7.x));
    float ay = ((a0.y + a1.y) + (a2.y + a3.y)) + ((a4.y + a5.y) + (a6.y + a7.y));
    ax *= ni; ay *= ni;
    if (HASB) { ax += bias[l * 2]; ay += bias[l * 2 + 1]; }
    if (RELU) { ax = fmaxf(ax, 0.0f); ay = fmaxf(ay, 0.0f); }
    float2 o; o.x = ax; o.y = ay;
    *(float2*)&hout[node * 64 + l * 2] = o;
}

// ---------------------------------------------------------------------------
// Dense GEMM — R2-proven design with padded W stride (KP = K+4):
//   sW[col*KP+k]: quarter-warp's 8 consecutive cols -> 16B-stepped banks,
//   conflict-free LDS.128. X loads are warp-broadcast. 16 FFMA per k4.
// ---------------------------------------------------------------------------
template<int K, int M, bool RELU>
__global__ void __launch_bounds__(256, 2)
gemm_kernel(const float* __restrict__ in,
            const float* __restrict__ W,
            const float* __restrict__ bias,
            const float* __restrict__ rowscale,
            float* __restrict__ out, int n) {
    constexpr int THREADS = 256;
    constexpr int RPAR = THREADS / M;
    constexpr int RPT = 4;
    constexpr int RTILE = RPAR * RPT;
    constexpr int KP = K + 4;
    __shared__ float sW[KP * M];
    __shared__ float sIn[RTILE * K];

    for (int idx = threadIdx.x; idx < K * M; idx += THREADS) {
        int k = idx / M, c = idx % M;
        sW[c * KP + k] = W[idx];
    }
    __syncthreads();

    int col = threadIdx.x % M;
    int rg  = threadIdx.x / M;
    const float4* wt = (const float4*)&sW[col * KP];

    int ntiles = (n + RTILE - 1) / RTILE;
    for (int t = blockIdx.x; t < ntiles; t += gridDim.x) {
        int row0 = t * RTILE;
        int rows = min(RTILE, n - row0);
        __syncthreads();
        {
            const float4* gin = (const float4*)&in[(size_t)row0 * K];
            float4* s4 = (float4*)sIn;
            int nv = rows * K / 4;
            for (int idx = threadIdx.x; idx < nv; idx += THREADS)
                s4[idx] = gin[idx];
        }
        __syncthreads();
        float acc[RPT];
        #pragma unroll
        for (int r = 0; r < RPT; r++) acc[r] = 0.0f;
        #pragma unroll
        for (int k4 = 0; k4 < K / 4; k4++) {
            float4 w = wt[k4];
            #pragma unroll
            for (int r = 0; r < RPT; r++) {
                int rr = rg + r * RPAR;
                float4 x = *(const float4*)&sIn[rr * K + k4 * 4];
                acc[r] = fmaf(w.x, x.x,
                         fmaf(w.y, x.y,
                         fmaf(w.z, x.z,
                         fmaf(w.w, x.w, acc[r]))));
            }
        }
        #pragma unroll
        for (int r = 0; r < RPT; r++) {
            int rr = rg + r * RPAR;
            if (rr < rows) {
                int row = row0 + rr;
                float v = acc[r];
                if (bias) v += bias[col];
                if (rowscale) v *= rowscale[row];
                if (RELU) v = fmaxf(v, 0.0f);
                out[(size_t)row * M + col] = v;
            }
        }
    }
}

// ---------------------------------------------------------------------------
// Fused: agg(h,32) *norm_in +b3, relu -> @W4[32,4] -> *norm_out
// ---------------------------------------------------------------------------
__global__ void agg32_gemm4(const float* __restrict__ hin,
                            const float* __restrict__ W4,
                            const float* __restrict__ b3,
                            float* __restrict__ hout, int n) {
    int warp = (blockIdx.x * blockDim.x + threadIdx.x) >> 5;
    int lane = threadIdx.x & 31;
    if (warp >= n) return;
    int node = warp;
    float4 w4 = *(const float4*)&W4[lane * 4];
    float bl = b3[lane];
    int beg = g_row_ptr[node], end = g_row_ptr[node + 1];
    const float* base = hin + lane;
    float a0 = 0, a1 = 0, a2 = 0, a3 = 0;
    float a4 = 0, a5 = 0, a6 = 0, a7 = 0;
    int e = beg;
    for (; e + 7 < end; e += 8) {
        a0 += base[g_csr_src[e] * 32];
        a1 += base[g_csr_src[e + 1] * 32];
        a2 += base[g_csr_src[e + 2] * 32];
        a3 += base[g_csr_src[e + 3] * 32];
        a4 += base[g_csr_src[e + 4] * 32];
        a5 += base[g_csr_src[e + 5] * 32];
        a6 += base[g_csr_src[e + 6] * 32];
        a7 += base[g_csr_src[e + 7] * 32];
    }
    for (; e < end; e++) a0 += base[g_csr_src[e] * 32];
    float a = ((a0 + a1) + (a2 + a3)) + ((a4 + a5) + (a6 + a7));
    a = fmaxf(fmaf(a, g_norm_in[node], bl), 0.0f);
    float4 y;
    y.x = a * w4.x; y.y = a * w4.y; y.z = a * w4.z; y.w = a * w4.w;
    #pragma unroll
    for (int o = 16; o; o >>= 1) {
        y.x += __shfl_xor_sync(0xffffffffu, y.x, o);
        y.y += __shfl_xor_sync(0xffffffffu, y.y, o);
        y.z += __shfl_xor_sync(0xffffffffu, y.z, o);
        y.w += __shfl_xor_sync(0xffffffffu, y.w, o);
    }
    if (lane == 0) {
        float s = g_norm_out[node];
        y.x *= s; y.y *= s; y.z *= s; y.w *= s;
        *(float4*)&hout[(size_t)node * 4] = y;
    }
}

// ---------------------------------------------------------------------------
// Final: agg(h,4) * norm_in + b4 -> per-graph atomic sum.
// ---------------------------------------------------------------------------
__global__ void agg4_readout(const float* __restrict__ hin,
                             const float* __restrict__ b4,
                             const int* __restrict__ gid, int n) {
    int warp = (blockIdx.x * blockDim.x + threadIdx.x) >> 5;
    int lane = threadIdx.x & 31;
    int node = warp * 8 + (lane >> 2);
    int l = lane & 3;
    float v = 0.f;
    int g = 0;
    bool valid = node < n;
    if (valid) {
        int beg = g_row_ptr[node], end = g_row_ptr[node + 1];
        float a0 = 0, a1 = 0, a2 = 0, a3 = 0;
        int e = beg;
        for (; e + 3 < end; e += 4) {
            a0 += hin[g_csr_src[e] * 4 + l];
            a1 += hin[g_csr_src[e + 1] * 4 + l];
            a2 += hin[g_csr_src[e + 2] * 4 + l];
            a3 += hin[g_csr_src[e + 3] * 4 + l];
        }
        for (; e < end; e++) a0 += hin[g_csr_src[e] * 4 + l];
        v = fmaf(((a0 + a1) + (a2 + a3)), g_norm_in[node], b4[l]);
        g = gid[node];
    }
    unsigned act = __ballot_sync(0xffffffffu, valid);
    if (act == 0xffffffffu) {
        int g0 = __shfl_sync(0xffffffffu, g, 0);
        if (__all_sync(0xffffffffu, g == g0)) {
            v += __shfl_xor_sync(0xffffffffu, v, 4);
            v += __shfl_xor_sync(0xffffffffu, v, 8);
            v += __shfl_xor_sync(0xffffffffu, v, 16);
            if (lane < 4) atomicAdd(&g_gsum[g0 * 4 + lane], v);
            return;
        }
    }
    if (valid) atomicAdd(&g_gsum[g * 4 + l], v);
}

// Per-graph mean; counts via binary search over sorted gid.
__global__ void graph_mean_kernel(float* __restrict__ out,
                                  const int* __restrict__ gid, int n, int g) {
    int i = blockIdx.x * blockDim.x + threadIdx.x;
    if (i >= g) return;
    int lo = 0, hi = n;
    while (lo < hi) { int mid = (lo + hi) >> 1; if (gid[mid] < i) lo = mid + 1; else hi = mid; }
    int lo2 = lo, hi2 = n;
    while (lo2 < hi2) { int mid = (lo2 + hi2) >> 1; if (gid[mid] < i + 1) lo2 = mid + 1; else hi2 = mid; }
    float c = fmaxf((float)(lo2 - lo), 1.0f);
    float4 sres = *(const float4*)&g_gsum[i * 4];
    out[i * 4 + 0] = sres.x / c;
    out[i * 4 + 1] = sres.y / c;
    out[i * 4 + 2] = sres.z / c;
    out[i * 4 + 3] = sres.w / c;
}

// ---------------------------------------------------------------------------
extern "C" void kernel_launch(void* const* d_in, const int* in_sizes, int n_in,
                              void* d_out, int out_size) {
    const float* x  = (const float*)d_in[0];
    const float* W1 = (const float*)d_in[1];
    const float* b1 = (const float*)d_in[2];
    const float* W2 = (const float*)d_in[3];
    const float* b2 = (const float*)d_in[4];
    const float* W3 = (const float*)d_in[5];
    const float* b3 = (const float*)d_in[6];
    const float* W4 = (const float*)d_in[7];
    const float* b4 = (const float*)d_in[8];
    const int* src = (const int*)d_in[9];
    const int* dst = (const int*)d_in[10];
    const int* gid = (const int*)d_in[11];
    float* out = (float*)d_out;

    int n = in_sizes[0] / 64;
    int e = in_sizes[9];
    int g = out_size / 4;
    int nsb = (n + 4095) / 4096;

    float *h0, *h1, *nrm_out;
    void *p_dego, *p_degi, *p_gsum, *p_sync;
    cudaGetSymbolAddress((void**)&h0, g_h0);
    cudaGetSymbolAddress((void**)&h1, g_h1);
    cudaGetSymbolAddress((void**)&nrm_out, g_norm_out);
    cudaGetSymbolAddress(&p_dego, g_deg_out);
    cudaGetSymbolAddress(&p_degi, g_deg_in);
    cudaGetSymbolAddress(&p_gsum, g_gsum);
    cudaGetSymbolAddress(&p_sync, g_sync);

    const int T = 256;
    auto blocks = [](int work, int t) { return (work + t - 1) / t; };
    auto warp_grid = [&](int nodes_per_warp) {
        int warps = (n + nodes_per_warp - 1) / nodes_per_warp;
        return (warps * 32 + T - 1) / T;
    };

    // Zeroing via memset nodes (not kernel launches)
    cudaMemsetAsync(p_dego, 0, (size_t)n * 4);
    cudaMemsetAsync(p_degi, 0, (size_t)n * 4);
    cudaMemsetAsync(p_gsum, 0, (size_t)g * 4 * 4);
    cudaMemsetAsync(p_sync, 0, 4 * 4);

    // Launch 1: fused preprocessing
    prep_kernel<<<148, 1024>>>(src, dst, n, e, nsb);

    const int GG = 296;  // 148 SMs * 2

    // Launch 2: agg(x * norm_out) -> *norm_in
    agg64_kernel<false, false, true><<<warp_grid(1), T>>>(x, h1, nullptr, n);
    // Launch 3: @W1 + b1, relu
    gemm_kernel<64, 128, true><<<GG, T>>>(h1, W1, b1, nullptr, h0, n);
    // Launch 4 (profiled): @W2, *norm_out
    gemm_kernel<128, 64, false><<<GG, T>>>(h0, W2, nullptr, nrm_out, h1, n);
    // Launch 5: agg -> *norm_in + b2, relu
    agg64_kernel<true, true, false><<<warp_grid(1), T>>>(h1, h0, b2, n);
    // Launch 6: @W3, *norm_out
    gemm_kernel<64, 32, false><<<GG, T>>>(h0, W3, nullptr, nrm_out, h1, n);
    // Launch 7: agg32 -> +b3, relu -> @W4 -> *norm_out
    agg32_gemm4<<<warp_grid(1), T>>>(h1, W4, b3, h0, n);
    // Launch 8: agg4 + readout
    agg4_readout<<<warp_grid(8), T>>>(h0, b4, gid, n);
    // Launch 9: per-graph mean
    graph_mean_kernel<<<blocks(g, T), T>>>(out, gid, n, g);
}

// round 13
// speedup vs baseline: 3.4642x; 1.3510x over previous
#include <cuda_runtime.h>

// ---------------------------------------------------------------------------
// GCN 4-layer forward on GB300 (sm_103a).
// R12: R11 skeleton + register-tiled GEMM (4 cols x 8 rows per thread):
// 12 LDS.128 per 128 FFMA per k4 -> FMA-bound under the measured
// "every LDS.128 = ~4 crossbar cycles" law (R11 profile evidence).
// ---------------------------------------------------------------------------

#define MAX_N 100000
#define MAX_E 800000
#define MAX_G 500

__device__ float g_norm_out[MAX_N];
__device__ float g_norm_in[MAX_N];
__device__ int   g_deg_out[MAX_N];
__device__ int   g_deg_in[MAX_N];
__device__ int   g_row_ptr[MAX_N + 1];
__device__ int   g_cursor[MAX_N];
__device__ int   g_csr_src[MAX_E];
__device__ float g_h0[MAX_N * 128];
__device__ float g_h1[MAX_N * 64];
__device__ float g_gsum[MAX_G * 4];
__device__ int   g_bsum[32];
__device__ int   g_sync[4];

// Device-wide barrier: all blocks co-resident (148 blocks, 1/SM).
__device__ __forceinline__ void gbar(int idx, int nb) {
    __syncthreads();
    if (threadIdx.x == 0) {
        __threadfence();
        atomicAdd(&g_sync[idx], 1);
        while (atomicAdd(&g_sync[idx], 0) < nb) { }
    }
    __syncthreads();
}

// ---------------------------------------------------------------------------
// Persistent preprocessing: degrees -> scan(+norms) -> csr_fill.
// ---------------------------------------------------------------------------
__global__ void __launch_bounds__(1024, 1)
prep_kernel(const int* __restrict__ src, const int* __restrict__ dst,
            int n, int e, int nsb) {
    const int NBK = gridDim.x;
    int b = blockIdx.x, t = threadIdx.x, lane = t & 31, w = t >> 5;
    int gtid = b * 1024 + t;
    int gsz = NBK * 1024;

    for (int i = gtid; i < e; i += gsz) {
        atomicAdd(&g_deg_out[src[i]], 1);
        atomicAdd(&g_deg_in[dst[i]], 1);
    }
    gbar(0, NBK);

    __shared__ int swarp[32];
    __shared__ int s_boff;
    int4 v = make_int4(0, 0, 0, 0);
    int s = 0, ts = 0;
    int i0 = b * 4096 + t * 4;
    if (b < nsb) {
        if (i0 + 3 < n) v = *(const int4*)&g_deg_in[i0];
        else {
            if (i0     < n) v.x = g_deg_in[i0];
            if (i0 + 1 < n) v.y = g_deg_in[i0 + 1];
            if (i0 + 2 < n) v.z = g_deg_in[i0 + 2];
            if (i0 + 3 < n) v.w = g_deg_in[i0 + 3];
        }
        if (i0 < n) {
            g_norm_in[i0] = rsqrtf(fmaxf((float)v.x, 1.f));
            g_norm_out[i0] = rsqrtf(fmaxf((float)g_deg_out[i0], 1.f));
        }
        if (i0 + 1 < n) {
            g_norm_in[i0 + 1] = rsqrtf(fmaxf((float)v.y, 1.f));
            g_norm_out[i0 + 1] = rsqrtf(fmaxf((float)g_deg_out[i0 + 1], 1.f));
        }
        if (i0 + 2 < n) {
            g_norm_in[i0 + 2] = rsqrtf(fmaxf((float)v.z, 1.f));
            g_norm_out[i0 + 2] = rsqrtf(fmaxf((float)g_deg_out[i0 + 2], 1.f));
        }
        if (i0 + 3 < n) {
            g_norm_in[i0 + 3] = rsqrtf(fmaxf((float)v.w, 1.f));
            g_norm_out[i0 + 3] = rsqrtf(fmaxf((float)g_deg_out[i0 + 3], 1.f));
        }
        ts = v.x + v.y + v.z + v.w;
        s = ts;
        #pragma unroll
        for (int o = 1; o < 32; o <<= 1) {
            int x = __shfl_up_sync(0xffffffffu, s, o);
            if (lane >= o) s += x;
        }
        if (lane == 31) swarp[w] = s;
        __syncthreads();
        if (w == 0) {
            int ws = swarp[lane];
            #pragma unroll
            for (int o = 1; o < 32; o <<= 1) {
                int x = __shfl_up_sync(0xffffffffu, ws, o);
                if (lane >= o) ws += x;
            }
            swarp[lane] = ws;
        }
        __syncthreads();
        if (t == 0) g_bsum[b] = swarp[31];
    }
    gbar(1, NBK);

    if (b < nsb) {
        if (w == 0) {
            int acc = (lane < b) ? g_bsum[lane] : 0;
            #pragma unroll
            for (int o = 16; o; o >>= 1) acc += __shfl_down_sync(0xffffffffu, acc, o);
            if (lane == 0) {
                s_boff = acc;
                if (b == nsb - 1) g_row_ptr[n] = acc + swarp[31];
            }
        }
        __syncthreads();
        int pre = (w > 0) ? swarp[w - 1] : 0;
        int e0 = s_boff + pre + s - ts;
        int e1 = e0 + v.x, e2 = e1 + v.y, e3 = e2 + v.z;
        if (i0     < n) { g_row_ptr[i0]     = e0; g_cursor[i0]     = e0; }
        if (i0 + 1 < n) { g_row_ptr[i0 + 1] = e1; g_cursor[i0 + 1] = e1; }
        if (i0 + 2 < n) { g_row_ptr[i0 + 2] = e2; g_cursor[i0 + 2] = e2; }
        if (i0 + 3 < n) { g_row_ptr[i0 + 3] = e3; g_cursor[i0 + 3] = e3; }
    }
    gbar(2, NBK);

    for (int i = gtid; i < e; i += gsz) {
        int p = atomicAdd(&g_cursor[dst[i]], 1);
        g_csr_src[p] = src[i];
    }
}

// ---------------------------------------------------------------------------
// Gather-aggregate DIM=64: warp/node, 8-way MLP unroll.
// ---------------------------------------------------------------------------
template<bool RELU, bool HASB, bool SRCSCALE>
__global__ void agg64_kernel(const float* __restrict__ hin,
                             float* __restrict__ hout,
                             const float* __restrict__ bias, int n) {
    int node = (blockIdx.x * blockDim.x + threadIdx.x) >> 5;
    int l = threadIdx.x & 31;
    if (node >= n) return;
    int beg = g_row_ptr[node];
    int end = g_row_ptr[node + 1];
    float ni = g_norm_in[node];
    const float* base = hin + l * 2;
    float2 a0 = {0,0}, a1 = {0,0}, a2 = {0,0}, a3 = {0,0};
    float2 a4 = {0,0}, a5 = {0,0}, a6 = {0,0}, a7 = {0,0};
    int e = beg;
    for (; e + 7 < end; e += 8) {
        int s0 = g_csr_src[e],     s1 = g_csr_src[e + 1];
        int s2 = g_csr_src[e + 2], s3 = g_csr_src[e + 3];
        int s4 = g_csr_src[e + 4], s5 = g_csr_src[e + 5];
        int s6 = g_csr_src[e + 6], s7 = g_csr_src[e + 7];
        float2 v0 = *(const float2*)(base + s0 * 64);
        float2 v1 = *(const float2*)(base + s1 * 64);
        float2 v2 = *(const float2*)(base + s2 * 64);
        float2 v3 = *(const float2*)(base + s3 * 64);
        float2 v4 = *(const float2*)(base + s4 * 64);
        float2 v5 = *(const float2*)(base + s5 * 64);
        float2 v6 = *(const float2*)(base + s6 * 64);
        float2 v7 = *(const float2*)(base + s7 * 64);
        if (SRCSCALE) {
            float n0 = g_norm_out[s0], n1 = g_norm_out[s1];
            float n2 = g_norm_out[s2], n3 = g_norm_out[s3];
            float n4 = g_norm_out[s4], n5 = g_norm_out[s5];
            float n6 = g_norm_out[s6], n7 = g_norm_out[s7];
            a0.x = fmaf(v0.x, n0, a0.x); a0.y = fmaf(v0.y, n0, a0.y);
            a1.x = fmaf(v1.x, n1, a1.x); a1.y = fmaf(v1.y, n1, a1.y);
            a2.x = fmaf(v2.x, n2, a2.x); a2.y = fmaf(v2.y, n2, a2.y);
            a3.x = fmaf(v3.x, n3, a3.x); a3.y = fmaf(v3.y, n3, a3.y);
            a4.x = fmaf(v4.x, n4, a4.x); a4.y = fmaf(v4.y, n4, a4.y);
            a5.x = fmaf(v5.x, n5, a5.x); a5.y = fmaf(v5.y, n5, a5.y);
            a6.x = fmaf(v6.x, n6, a6.x); a6.y = fmaf(v6.y, n6, a6.y);
            a7.x = fmaf(v7.x, n7, a7.x); a7.y = fmaf(v7.y, n7, a7.y);
        } else {
            a0.x += v0.x; a0.y += v0.y; a1.x += v1.x; a1.y += v1.y;
            a2.x += v2.x; a2.y += v2.y; a3.x += v3.x; a3.y += v3.y;
            a4.x += v4.x; a4.y += v4.y; a5.x += v5.x; a5.y += v5.y;
            a6.x += v6.x; a6.y += v6.y; a7.x += v7.x; a7.y += v7.y;
        }
    }
    for (; e < end; e++) {
        int s0 = g_csr_src[e];
        float2 v = *(const float2*)(base + s0 * 64);
        if (SRCSCALE) {
            float n0 = g_norm_out[s0];
            a0.x = fmaf(v.x, n0, a0.x); a0.y = fmaf(v.y, n0, a0.y);
        } else { a0.x += v.x; a0.y += v.y; }
    }
    float ax = ((a0.x + a1.x) + (a2.x + a3.x)) + ((a4.x + a5.x) + (a6.x + a7.x));
    float ay = ((a0.y + a1.y) + (a2.y + a3.y)) + ((a4.y + a5.y) + (a6.y + a7.y));
    ax *= ni; ay *= ni;
    if (HASB) { ax += bias[l * 2]; ay += bias[l * 2 + 1]; }
    if (RELU) { ax = fmaxf(ax, 0.0f); ay = fmaxf(ay, 0.0f); }
    float2 o; o.x = ax; o.y = ay;
    *(float2*)&hout[node * 64 + l * 2] = o;
}

// ---------------------------------------------------------------------------
// Register-tiled GEMM: out[N,M] = op(in[N,K] @ W[K,M]).
// Thread tile: 4 cols (one col-group cg) x R rows (strided rg + r*RPAR).
// sW4[k*CGT+cg] = float4 of cols [4cg..4cg+3] at row k  (contiguous copy of W)
// sIn rows padded to K+4 floats -> per-warp X loads land on distinct banks.
// Per k4: 4 W-LDS.128 + R X-LDS.128 for 16R FFMA  (R=8 -> 12 LDS / 128 FFMA).
// ---------------------------------------------------------------------------
template<int K, int M, int R, bool RELU, bool BIAS, bool RSCALE, int MAXB>
__global__ void __launch_bounds__(256, MAXB)
gemm_kernel(const float* __restrict__ in, const float* __restrict__ W,
            const float* __restrict__ bias, float* __restrict__ out, int n) {
    constexpr int THREADS = 256;
    constexpr int CGT = M / 4;
    constexpr int RPAR = THREADS / CGT;
    constexpr int RTILE = RPAR * R;
    constexpr int KV = K / 4;
    constexpr int KP = K + 4;

    extern __shared__ char smx[];
    float4* sW4 = (float4*)smx;                       // K*CGT float4
    float*  sIn = (float*)(smx + (size_t)K * CGT * 16); // RTILE*KP floats

    const int tid = threadIdx.x;
    for (int idx = tid; idx < K * CGT; idx += THREADS)
        sW4[idx] = ((const float4*)W)[idx];

    int cg = tid % CGT;
    int rg = tid / CGT;
    int c0 = cg * 4;

    float4 bv = make_float4(0.f, 0.f, 0.f, 0.f);
    if (BIAS) bv = *(const float4*)&bias[c0];

    const float4* in4 = (const float4*)in;
    int ntiles = (n + RTILE - 1) / RTILE;
    for (int t = blockIdx.x; t < ntiles; t += gridDim.x) {
        int row0 = t * RTILE;
        __syncthreads();
        for (int idx = tid; idx < RTILE * KV; idx += THREADS) {
            int r = idx / KV, k4 = idx % KV;
            int row = row0 + r;
            float4 v = (row < n) ? in4[(size_t)row * KV + k4]
                                 : make_float4(0.f, 0.f, 0.f, 0.f);
            *(float4*)&sIn[r * KP + k4 * 4] = v;
        }
        __syncthreads();

        float4 acc[R];
        #pragma unroll
        for (int r = 0; r < R; r++) acc[r] = make_float4(0.f, 0.f, 0.f, 0.f);

        #pragma unroll 2
        for (int k4 = 0; k4 < KV; k4++) {
            float4 w0 = sW4[(k4 * 4 + 0) * CGT + cg];
            float4 w1 = sW4[(k4 * 4 + 1) * CGT + cg];
            float4 w2 = sW4[(k4 * 4 + 2) * CGT + cg];
            float4 w3 = sW4[(k4 * 4 + 3) * CGT + cg];
            #pragma unroll
            for (int r = 0; r < R; r++) {
                float4 x = *(const float4*)&sIn[(rg + r * RPAR) * KP + k4 * 4];
                acc[r].x = fmaf(x.x, w0.x, fmaf(x.y, w1.x, fmaf(x.z, w2.x, fmaf(x.w, w3.x, acc[r].x))));
                acc[r].y = fmaf(x.x, w0.y, fmaf(x.y, w1.y, fmaf(x.z, w2.y, fmaf(x.w, w3.y, acc[r].y))));
                acc[r].z = fmaf(x.x, w0.z, fmaf(x.y, w1.z, fmaf(x.z, w2.z, fmaf(x.w, w3.z, acc[r].z))));
                acc[r].w = fmaf(x.x, w0.w, fmaf(x.y, w1.w, fmaf(x.z, w2.w, fmaf(x.w, w3.w, acc[r].w))));
            }
        }

        #pragma unroll
        for (int r = 0; r < R; r++) {
            int row = row0 + rg + r * RPAR;
            if (row < n) {
                float4 v = acc[r];
                if (BIAS) { v.x += bv.x; v.y += bv.y; v.z += bv.z; v.w += bv.w; }
                if (RSCALE) {
                    float rs = g_norm_out[row];
                    v.x *= rs; v.y *= rs; v.z *= rs; v.w *= rs;
                }
                if (RELU) {
                    v.x = fmaxf(v.x, 0.f); v.y = fmaxf(v.y, 0.f);
                    v.z = fmaxf(v.z, 0.f); v.w = fmaxf(v.w, 0.f);
                }
                *(float4*)&out[(size_t)row * M + c0] = v;
            }
        }
    }
}

// ---------------------------------------------------------------------------
// Fused: agg(h,32) *norm_in +b3, relu -> @W4[32,4] -> *norm_out
// ---------------------------------------------------------------------------
__global__ void agg32_gemm4(const float* __restrict__ hin,
                            const float* __restrict__ W4,
                            const float* __restrict__ b3,
                            float* __restrict__ hout, int n) {
    int warp = (blockIdx.x * blockDim.x + threadIdx.x) >> 5;
    int lane = threadIdx.x & 31;
    if (warp >= n) return;
    int node = warp;
    float4 w4 = *(const float4*)&W4[lane * 4];
    float bl = b3[lane];
    int beg = g_row_ptr[node], end = g_row_ptr[node + 1];
    const float* base = hin + lane;
    float a0 = 0, a1 = 0, a2 = 0, a3 = 0;
    float a4 = 0, a5 = 0, a6 = 0, a7 = 0;
    int e = beg;
    for (; e + 7 < end; e += 8) {
        a0 += base[g_csr_src[e] * 32];
        a1 += base[g_csr_src[e + 1] * 32];
        a2 += base[g_csr_src[e + 2] * 32];
        a3 += base[g_csr_src[e + 3] * 32];
        a4 += base[g_csr_src[e + 4] * 32];
        a5 += base[g_csr_src[e + 5] * 32];
        a6 += base[g_csr_src[e + 6] * 32];
        a7 += base[g_csr_src[e + 7] * 32];
    }
    for (; e < end; e++) a0 += base[g_csr_src[e] * 32];
    float a = ((a0 + a1) + (a2 + a3)) + ((a4 + a5) + (a6 + a7));
    a = fmaxf(fmaf(a, g_norm_in[node], bl), 0.0f);
    float4 y;
    y.x = a * w4.x; y.y = a * w4.y; y.z = a * w4.z; y.w = a * w4.w;
    #pragma unroll
    for (int o = 16; o; o >>= 1) {
        y.x += __shfl_xor_sync(0xffffffffu, y.x, o);
        y.y += __shfl_xor_sync(0xffffffffu, y.y, o);
        y.z += __shfl_xor_sync(0xffffffffu, y.z, o);
        y.w += __shfl_xor_sync(0xffffffffu, y.w, o);
    }
    if (lane == 0) {
        float s = g_norm_out[node];
        y.x *= s; y.y *= s; y.z *= s; y.w *= s;
        *(float4*)&hout[(size_t)node * 4] = y;
    }
}

// ---------------------------------------------------------------------------
// Final: agg(h,4) * norm_in + b4 -> per-graph atomic sum.
// ---------------------------------------------------------------------------
__global__ void agg4_readout(const float* __restrict__ hin,
                             const float* __restrict__ b4,
                             const int* __restrict__ gid, int n) {
    int warp = (blockIdx.x * blockDim.x + threadIdx.x) >> 5;
    int lane = threadIdx.x & 31;
    int node = warp * 8 + (lane >> 2);
    int l = lane & 3;
    float v = 0.f;
    int g = 0;
    bool valid = node < n;
    if (valid) {
        int beg = g_row_ptr[node], end = g_row_ptr[node + 1];
        float a0 = 0, a1 = 0, a2 = 0, a3 = 0;
        int e = beg;
        for (; e + 3 < end; e += 4) {
            a0 += hin[g_csr_src[e] * 4 + l];
            a1 += hin[g_csr_src[e + 1] * 4 + l];
            a2 += hin[g_csr_src[e + 2] * 4 + l];
            a3 += hin[g_csr_src[e + 3] * 4 + l];
        }
        for (; e < end; e++) a0 += hin[g_csr_src[e] * 4 + l];
        v = fmaf(((a0 + a1) + (a2 + a3)), g_norm_in[node], b4[l]);
        g = gid[node];
    }
    unsigned act = __ballot_sync(0xffffffffu, valid);
    if (act == 0xffffffffu) {
        int g0 = __shfl_sync(0xffffffffu, g, 0);
        if (__all_sync(0xffffffffu, g == g0)) {
            v += __shfl_xor_sync(0xffffffffu, v, 4);
            v += __shfl_xor_sync(0xffffffffu, v, 8);
            v += __shfl_xor_sync(0xffffffffu, v, 16);
            if (lane < 4) atomicAdd(&g_gsum[g0 * 4 + lane], v);
            return;
        }
    }
    if (valid) atomicAdd(&g_gsum[g * 4 + l], v);
}

// Per-graph mean; counts via binary search over sorted gid.
__global__ void graph_mean_kernel(float* __restrict__ out,
                                  const int* __restrict__ gid, int n, int g) {
    int i = blockIdx.x * blockDim.x + threadIdx.x;
    if (i >= g) return;
    int lo = 0, hi = n;
    while (lo < hi) { int mid = (lo + hi) >> 1; if (gid[mid] < i) lo = mid + 1; else hi = mid; }
    int lo2 = lo, hi2 = n;
    while (lo2 < hi2) { int mid = (lo2 + hi2) >> 1; if (gid[mid] < i + 1) lo2 = mid + 1; else hi2 = mid; }
    float c = fmaxf((float)(lo2 - lo), 1.0f);
    float4 sres = *(const float4*)&g_gsum[i * 4];
    out[i * 4 + 0] = sres.x / c;
    out[i * 4 + 1] = sres.y / c;
    out[i * 4 + 2] = sres.z / c;
    out[i * 4 + 3] = sres.w / c;
}

// ---------------------------------------------------------------------------
extern "C" void kernel_launch(void* const* d_in, const int* in_sizes, int n_in,
                              void* d_out, int out_size) {
    const float* x  = (const float*)d_in[0];
    const float* W1 = (const float*)d_in[1];
    const float* b1 = (const float*)d_in[2];
    const float* W2 = (const float*)d_in[3];
    const float* b2 = (const float*)d_in[4];
    const float* W3 = (const float*)d_in[5];
    const float* b3 = (const float*)d_in[6];
    const float* W4 = (const float*)d_in[7];
    const float* b4 = (const float*)d_in[8];
    const int* src = (const int*)d_in[9];
    const int* dst = (const int*)d_in[10];
    const int* gid = (const int*)d_in[11];
    float* out = (float*)d_out;

    int n = in_sizes[0] / 64;
    int e = in_sizes[9];
    int g = out_size / 4;
    int nsb = (n + 4095) / 4096;

    float *h0, *h1;
    void *p_dego, *p_degi, *p_gsum, *p_sync;
    cudaGetSymbolAddress((void**)&h0, g_h0);
    cudaGetSymbolAddress((void**)&h1, g_h1);
    cudaGetSymbolAddress(&p_dego, g_deg_out);
    cudaGetSymbolAddress(&p_degi, g_deg_in);
    cudaGetSymbolAddress(&p_gsum, g_gsum);
    cudaGetSymbolAddress(&p_sync, g_sync);

    const int T = 256;
    auto blocks = [](int work, int t) { return (work + t - 1) / t; };
    auto warp_grid = [&](int nodes_per_warp) {
        int warps = (n + nodes_per_warp - 1) / nodes_per_warp;
        return (warps * 32 + T - 1) / T;
    };

    // GEMM smem: sW4 = K*(M/4)*16B, sIn = RTILE*(K+4)*4B
    // gemm1 (64->128, R=8):  RTILE=64:  32768 + 64*68*4  = 50176  (occ 3)
    // gemm2 (128->64, R=8):  RTILE=128: 32768 + 128*132*4 = 100352 (occ 2)
    // gemm3 (64->32,  R=8):  RTILE=256: 8192  + 256*68*4  = 77824  (occ 2)
    const int SM1 = 64 * 32 * 16 + 64 * 68 * 4;
    const int SM2 = 128 * 16 * 16 + 128 * 132 * 4;
    const int SM3 = 64 * 8 * 16 + 256 * 68 * 4;
    cudaFuncSetAttribute((const void*)gemm_kernel<64, 128, 8, true, true, false, 3>,
                         cudaFuncAttributeMaxDynamicSharedMemorySize, SM1);
    cudaFuncSetAttribute((const void*)gemm_kernel<128, 64, 8, false, false, true, 2>,
                         cudaFuncAttributeMaxDynamicSharedMemorySize, SM2);
    cudaFuncSetAttribute((const void*)gemm_kernel<64, 32, 8, false, false, true, 2>,
                         cudaFuncAttributeMaxDynamicSharedMemorySize, SM3);

    // Zeroing via memset nodes (not kernel launches)
    cudaMemsetAsync(p_dego, 0, (size_t)n * 4);
    cudaMemsetAsync(p_degi, 0, (size_t)n * 4);
    cudaMemsetAsync(p_gsum, 0, (size_t)g * 4 * 4);
    cudaMemsetAsync(p_sync, 0, 4 * 4);

    // Launch 1: fused preprocessing
    prep_kernel<<<148, 1024>>>(src, dst, n, e, nsb);

    // Launch 2: agg(x * norm_out) -> *norm_in
    agg64_kernel<false, false, true><<<warp_grid(1), T>>>(x, h1, nullptr, n);
    // Launch 3: @W1 + b1, relu
    gemm_kernel<64, 128, 8, true, true, false, 3><<<444, T, SM1>>>(h1, W1, b1, h0, n);
    // Launch 4 (profiled): @W2, *norm_out
    gemm_kernel<128, 64, 8, false, false, true, 2><<<296, T, SM2>>>(h0, W2, nullptr, h1, n);
    // Launch 5: agg -> *norm_in + b2, relu
    agg64_kernel<true, true, false><<<warp_grid(1), T>>>(h1, h0, b2, n);
    // Launch 6: @W3, *norm_out
    gemm_kernel<64, 32, 8, false, false, true, 2><<<296, T, SM3>>>(h0, W3, nullptr, h1, n);
    // Launch 7: agg32 -> +b3, relu -> @W4 -> *norm_out
    agg32_gemm4<<<warp_grid(1), T>>>(h1, W4, b3, h0, n);
    // Launch 8: agg4 + readout
    agg4_readout<<<warp_grid(8), T>>>(h0, b4, gid, n);
    // Launch 9: per-graph mean
    graph_mean_kernel<<<blocks(g, T), T>>>(out, gid, n, g);
}